// round 13
// baseline (speedup 1.0000x reference)
#include <cuda_runtime.h>
#include <math.h>

#define B 16
#define C 256
#define H 128
#define W 128
#define HW (H*W)
#define R 16
#define CSPLIT 4
#define CCHUNK (C/CSPLIT)   // 64

typedef unsigned long long ull;

// Scratch (allocation-free: __device__ globals)
__device__ float  g_avg[B*C];
__device__ float  g_max[B*C];
__device__ float  g_wch[B*C];
__device__ float2 g_part[CSPLIT][B*HW]; // partial (max,sum) per channel-chunk
__device__ float2 g_cat2[B*HW];         // interleaved (maxmap, avgmap) per pixel
__device__ float  g_ws[B*HW];

// ---- packed f32x2 helpers (sm_100+) ----
__device__ __forceinline__ ull pack2(float a, float b) {
    ull r; asm("mov.b64 %0, {%1, %2};" : "=l"(r) : "f"(a), "f"(b)); return r;
}
__device__ __forceinline__ float2 unpack2(ull v) {
    float2 r; asm("mov.b64 {%0, %1}, %2;" : "=f"(r.x), "=f"(r.y) : "l"(v)); return r;
}
__device__ __forceinline__ ull ffma2(ull a, ull b, ull c) {
    ull d; asm("fma.rn.f32x2 %0, %1, %2, %3;" : "=l"(d) : "l"(a), "l"(b), "l"(c)); return d;
}
__device__ __forceinline__ ull fadd2(ull a, ull b) {
    ull d; asm("add.rn.f32x2 %0, %1, %2;" : "=l"(d) : "l"(a), "l"(b)); return d;
}
// streaming (evict-first) float4 load/store
__device__ __forceinline__ float4 ldcs4(const float4* p) {
    float4 v;
    asm("ld.global.cs.v4.f32 {%0,%1,%2,%3}, [%4];"
        : "=f"(v.x), "=f"(v.y), "=f"(v.z), "=f"(v.w) : "l"(p));
    return v;
}
__device__ __forceinline__ void stcs4(float4* p, float4 v) {
    asm volatile("st.global.cs.v4.f32 [%0], {%1,%2,%3,%4};"
                 :: "l"(p), "f"(v.x), "f"(v.y), "f"(v.z), "f"(v.w));
}

// ---------------- K1: per-(b,c) mean & max over H,W ----------------
__global__ __launch_bounds__(512) void k_reduce_hw(const float* __restrict__ x) {
    int bc = blockIdx.x;
    const float4* xp = (const float4*)(x + (size_t)bc * HW);
    float s0 = 0.f, s1 = 0.f, s2 = 0.f, s3 = 0.f;
    float m0 = -INFINITY, m1 = -INFINITY, m2 = -INFINITY, m3 = -INFINITY;
    #pragma unroll
    for (int i = threadIdx.x; i < HW/16; i += 512) {
        float4 v0 = ldcs4(&xp[i]);
        float4 v1 = ldcs4(&xp[i +   HW/16]);
        float4 v2 = ldcs4(&xp[i + 2*HW/16]);
        float4 v3 = ldcs4(&xp[i + 3*HW/16]);
        s0 += (v0.x + v0.y) + (v0.z + v0.w);
        s1 += (v1.x + v1.y) + (v1.z + v1.w);
        s2 += (v2.x + v2.y) + (v2.z + v2.w);
        s3 += (v3.x + v3.y) + (v3.z + v3.w);
        m0 = fmaxf(m0, fmaxf(fmaxf(v0.x, v0.y), fmaxf(v0.z, v0.w)));
        m1 = fmaxf(m1, fmaxf(fmaxf(v1.x, v1.y), fmaxf(v1.z, v1.w)));
        m2 = fmaxf(m2, fmaxf(fmaxf(v2.x, v2.y), fmaxf(v2.z, v2.w)));
        m3 = fmaxf(m3, fmaxf(fmaxf(v3.x, v3.y), fmaxf(v3.z, v3.w)));
    }
    float s = (s0 + s1) + (s2 + s3);
    float m = fmaxf(fmaxf(m0, m1), fmaxf(m2, m3));
    #pragma unroll
    for (int o = 16; o; o >>= 1) {
        s += __shfl_xor_sync(0xffffffffu, s, o);
        m = fmaxf(m, __shfl_xor_sync(0xffffffffu, m, o));
    }
    __shared__ float ss[16], sm[16];
    int w = threadIdx.x >> 5, l = threadIdx.x & 31;
    if (l == 0) { ss[w] = s; sm[w] = m; }
    __syncthreads();
    if (threadIdx.x == 0) {
        for (int i = 1; i < 16; i++) { s += ss[i]; m = fmaxf(m, sm[i]); }
        g_avg[bc] = s * (1.f / HW);
        g_max[bc] = m;
    }
}

// ---------------- K2: channel MLP -> wch (tiny, grid=B) ----------------
__global__ __launch_bounds__(256) void k_mlp(const float* __restrict__ w1, const float* __restrict__ b1,
                                             const float* __restrict__ w2, const float* __restrict__ b2) {
    int b = blockIdx.x;
    int t = threadIdx.x;
    __shared__ float s_avg[C], s_mx[C], s_h[R];
    s_avg[t] = g_avg[b*C + t];
    s_mx[t]  = g_max[b*C + t];
    __syncthreads();
    if (t < R) {
        float ha = b1[t], hm = b1[t];
        #pragma unroll 8
        for (int c = 0; c < C; c++) {
            float w = __ldg(&w1[t*C + c]);
            ha = fmaf(w, s_avg[c], ha);
            hm = fmaf(w, s_mx[c],  hm);
        }
        s_h[t] = fmaxf(ha, 0.f) + fmaxf(hm, 0.f);
    }
    __syncthreads();
    float o = 2.f * __ldg(&b2[t]);
    #pragma unroll
    for (int r = 0; r < R; r++) o = fmaf(__ldg(&w2[t*R + r]), s_h[r], o);
    g_wch[b*C + t] = 1.f / (1.f + __expf(-o));
}

// ---------------- K3: partial cat maps over 64 channels ----------------
// grid (HW/4/256, B, CSPLIT), block 256
__global__ __launch_bounds__(256) void k_cat(const float* __restrict__ x) {
    int b  = blockIdx.y;
    int cz = blockIdx.z;
    int t  = threadIdx.x;
    __shared__ float sw[CCHUNK];
    if (t < CCHUNK) sw[t] = g_wch[b*C + cz*CCHUNK + t];
    __syncthreads();

    int p4 = blockIdx.x * 256 + t;   // float4 index within HW
    const float4* xb = (const float4*)(x + (size_t)b * C * HW + (size_t)cz*CCHUNK*HW);
    float4 s0 = make_float4(0.f,0.f,0.f,0.f), s1 = s0;
    float4 m0 = make_float4(-INFINITY,-INFINITY,-INFINITY,-INFINITY), m1 = m0;
    #pragma unroll 8
    for (int c = 0; c < CCHUNK; c += 2) {
        float4 v0 = ldcs4(&xb[(size_t)c     * (HW/4) + p4]);
        float4 v1 = ldcs4(&xb[(size_t)(c+1) * (HW/4) + p4]);
        float w0 = sw[c], w1v = sw[c+1];
        float a0 = w0*v0.x, a1 = w0*v0.y, a2 = w0*v0.z, a3 = w0*v0.w;
        float b0 = w1v*v1.x, b1v = w1v*v1.y, b2v = w1v*v1.z, b3 = w1v*v1.w;
        s0.x += a0; s0.y += a1; s0.z += a2; s0.w += a3;
        s1.x += b0; s1.y += b1v; s1.z += b2v; s1.w += b3;
        m0.x = fmaxf(m0.x, a0); m0.y = fmaxf(m0.y, a1);
        m0.z = fmaxf(m0.z, a2); m0.w = fmaxf(m0.w, a3);
        m1.x = fmaxf(m1.x, b0); m1.y = fmaxf(m1.y, b1v);
        m1.z = fmaxf(m1.z, b2v); m1.w = fmaxf(m1.w, b3);
    }
    float4 s = make_float4(s0.x+s1.x, s0.y+s1.y, s0.z+s1.z, s0.w+s1.w);
    float4 m = make_float4(fmaxf(m0.x,m1.x), fmaxf(m0.y,m1.y), fmaxf(m0.z,m1.z), fmaxf(m0.w,m1.w));

    float4* dst = (float4*)(g_part[cz] + (size_t)b*HW + (size_t)p4*4);
    dst[0] = make_float4(m.x, s.x, m.y, s.y);
    dst[1] = make_float4(m.z, s.z, m.w, s.w);
}

// ---------------- K3b: combine the CSPLIT partials -> g_cat2 ----------------
// one thread per pixel (float2) for max latency-hiding parallelism
__global__ __launch_bounds__(256) void k_combine() {
    int i = blockIdx.x * blockDim.x + threadIdx.x;   // 0 .. B*HW-1
    float2 a = g_part[0][i];
    float2 c = g_part[1][i];
    float2 d = g_part[2][i];
    float2 e = g_part[3][i];
    const float inv = 1.f / C;
    float2 o;
    o.x = fmaxf(fmaxf(a.x, c.x), fmaxf(d.x, e.x));
    o.y = ((a.y + c.y) + (d.y + e.y)) * inv;
    g_cat2[i] = o;
}

// ---------------- K4: offsets conv + deform conv + BN + sigmoid -> ws ----------------
// 2 pixels per thread (rows i0, i0+1); 4 independent FFMA2 chains per pixel-tap.
__global__ __launch_bounds__(128)
void k_deform(const float* __restrict__ off_w, const float* __restrict__ off_b,
              const float* __restrict__ dc_w,  const float* __restrict__ dc_b,
              const float* __restrict__ bn_gamma, const float* __restrict__ bn_beta,
              const float* __restrict__ bn_mean,  const float* __restrict__ bn_var) {
    __shared__ ull   s_wp[9][18];     // [tap][q] = (w_dy[q], w_dx[q])
    __shared__ ull   s_obp[9];        // (off_b[2k], off_b[2k+1])
    __shared__ float s_dw[18];
    __shared__ float2 trow[4][W];     // rows i0-1 .. i0+2 of (max,avg)

    int b  = blockIdx.x >> 6;
    int i0 = (blockIdx.x & 63) * 2;
    int j  = threadIdx.x;

    for (int t = threadIdx.x; t < 162; t += 128) {
        int k = t / 18, q = t - k*18;
        s_wp[k][q] = pack2(off_w[(2*k)*18 + q], off_w[(2*k+1)*18 + q]);
    }
    if (threadIdx.x < 9)  s_obp[threadIdx.x] = pack2(off_b[2*threadIdx.x], off_b[2*threadIdx.x + 1]);
    if (threadIdx.x < 18) s_dw[threadIdx.x]  = dc_w[threadIdx.x];

    const float2* c2 = g_cat2 + (size_t)b*HW;

    #pragma unroll
    for (int r = 0; r < 4; r++) {
        int yy = i0 + r - 1;
        bool ok = (unsigned)yy < H;
        trow[r][j] = ok ? c2[yy*W + j] : make_float2(0.f, 0.f);
    }
    __syncthreads();

    ull na[4][3], nb[4][3];
    #pragma unroll
    for (int u = 0; u < 4; u++) {
        #pragma unroll
        for (int v = 0; v < 3; v++) {
            int xx = j + v - 1;
            bool ok = (unsigned)xx < W;
            int xc = min(max(xx, 0), W-1);
            float2 val = trow[u][xc];
            float vx = ok ? val.x : 0.f;
            float vy = ok ? val.y : 0.f;
            na[u][v] = pack2(vx, vx);
            nb[u][v] = pack2(vy, vy);
        }
    }

    const float dcb = __ldg(dc_b);
    float acc0 = dcb, acc1 = dcb;
    const float fj = (float)j;
    const float fi0 = (float)i0, fi1 = (float)(i0 + 1);

    #pragma unroll
    for (int k = 0; k < 9; k++) {
        const int ky = k / 3, kx = k % 3;
        ull p0a = s_obp[k], p0b = 0ull, p0c = 0ull, p0d = 0ull;
        ull p1a = s_obp[k], p1b = 0ull, p1c = 0ull, p1d = 0ull;
        #pragma unroll
        for (int q = 0; q < 9; q++) {
            int u = q / 3, v = q - u*3;
            ull w = s_wp[k][q];
            if (q < 5) { p0a = ffma2(w, na[u][v], p0a); p1a = ffma2(w, na[u+1][v], p1a); }
            else       { p0b = ffma2(w, na[u][v], p0b); p1b = ffma2(w, na[u+1][v], p1b); }
        }
        #pragma unroll
        for (int q = 0; q < 9; q++) {
            int u = q / 3, v = q - u*3;
            ull w = s_wp[k][9 + q];
            if (q < 5) { p0c = ffma2(w, nb[u][v], p0c); p1c = ffma2(w, nb[u+1][v], p1c); }
            else       { p0d = ffma2(w, nb[u][v], p0d); p1d = ffma2(w, nb[u+1][v], p1d); }
        }
        ull a0 = fadd2(fadd2(p0a, p0b), fadd2(p0c, p0d));
        ull a1 = fadd2(fadd2(p1a, p1b), fadd2(p1c, p1d));
        float2 o0 = unpack2(a0);
        float2 o1 = unpack2(a1);

        #pragma unroll
        for (int p = 0; p < 2; p++) {
            float py = (p ? fi1 : fi0) + (float)(ky - 1) + (p ? o1.x : o0.x);
            float px = fj + (float)(kx - 1) + (p ? o1.y : o0.y);
            float y0f = floorf(py), x0f = floorf(px);
            float wy = py - y0f, wx = px - x0f;
            float omwy = 1.f - wy, omwx = 1.f - wx;
            int y0 = (int)y0f, x0 = (int)x0f;

            ull s00 = 0ull, s01 = 0ull;
            #pragma unroll
            for (int dy = 0; dy < 2; dy++) {
                #pragma unroll
                for (int dx = 0; dx < 2; dx++) {
                    int yi = y0 + dy, xi = x0 + dx;
                    bool ok = ((unsigned)yi < H) & ((unsigned)xi < W);
                    float wgt = (dy ? wy : omwy) * (dx ? wx : omwx);
                    wgt = ok ? wgt : 0.f;
                    int idx = min(max(yi, 0), H-1) * W + min(max(xi, 0), W-1);
                    ull v = *(const ull*)(c2 + idx);
                    if (dy) s01 = ffma2(v, pack2(wgt, wgt), s01);
                    else    s00 = ffma2(v, pack2(wgt, wgt), s00);
                }
            }
            float2 sv = unpack2(fadd2(s00, s01));
            if (p) {
                acc1 = fmaf(sv.x, s_dw[k],     acc1);
                acc1 = fmaf(sv.y, s_dw[9 + k], acc1);
            } else {
                acc0 = fmaf(sv.x, s_dw[k],     acc0);
                acc0 = fmaf(sv.y, s_dw[9 + k], acc0);
            }
        }
    }

    float inv = __ldg(bn_gamma) * rsqrtf(__ldg(bn_var) + 1e-5f);
    float mean = __ldg(bn_mean), beta = __ldg(bn_beta);
    float d0 = (acc0 - mean) * inv + beta;
    float d1 = (acc1 - mean) * inv + beta;
    g_ws[b*HW + i0*W + j]       = 1.f / (1.f + __expf(-d0));
    g_ws[b*HW + (i0+1)*W + j]   = 1.f / (1.f + __expf(-d1));
}

// ---------------- K5: out = x * (1 + wch*ws) ----------------
// 4 float4 per thread; block covers 1024 consecutive float4 (one (b,c) slice
// spans 1024 float4, so c changes at most once -> but we keep per-chunk c).
__global__ __launch_bounds__(256) void k_final(const float* __restrict__ x, float* __restrict__ out) {
    size_t base = (size_t)blockIdx.x * 1024 + threadIdx.x;   // float4 index
    #pragma unroll
    for (int r = 0; r < 4; r++) {
        size_t i4 = base + r*256;
        size_t e  = i4 << 2;
        int b  = (int)(e >> 22);            // C*HW = 2^22
        int c  = (int)(e >> 14) & (C - 1);
        int hw = (int)e & (HW - 1);
        float w = __ldg(&g_wch[b*C + c]);
        float4 xv = ldcs4((const float4*)x + i4);
        float4 wv = __ldg((const float4*)(g_ws + (size_t)b*HW) + (hw >> 2));
        float4 o;
        o.x = xv.x * fmaf(w, wv.x, 1.f);
        o.y = xv.y * fmaf(w, wv.y, 1.f);
        o.z = xv.z * fmaf(w, wv.z, 1.f);
        o.w = xv.w * fmaf(w, wv.w, 1.f);
        stcs4((float4*)out + i4, o);
    }
}

extern "C" void kernel_launch(void* const* d_in, const int* in_sizes, int n_in,
                              void* d_out, int out_size) {
    const float* x     = (const float*)d_in[0];
    const float* w1    = (const float*)d_in[1];
    const float* b1    = (const float*)d_in[2];
    const float* w2    = (const float*)d_in[3];
    const float* b2    = (const float*)d_in[4];
    const float* off_w = (const float*)d_in[5];
    const float* off_b = (const float*)d_in[6];
    const float* dc_w  = (const float*)d_in[7];
    const float* dc_b  = (const float*)d_in[8];
    const float* bng   = (const float*)d_in[9];
    const float* bnb   = (const float*)d_in[10];
    const float* bnm   = (const float*)d_in[11];
    const float* bnv   = (const float*)d_in[12];
    float* out = (float*)d_out;

    k_reduce_hw<<<B*C, 512>>>(x);
    k_mlp<<<B, C>>>(w1, b1, w2, b2);
    {
        dim3 grid(HW/4/256, B, CSPLIT);
        k_cat<<<grid, 256>>>(x);
    }
    k_combine<<<(B*HW)/256, 256>>>();
    k_deform<<<B*H/2, 128>>>(off_w, off_b, dc_w, dc_b, bng, bnb, bnm, bnv);
    k_final<<<(B*C*HW)/4/1024, 256>>>(x, out);
}

// round 14
// speedup vs baseline: 1.0571x; 1.0571x over previous
#include <cuda_runtime.h>
#include <math.h>

#define B 16
#define C 256
#define H 128
#define W 128
#define HW (H*W)
#define R 16
#define CSPLIT 4
#define CCHUNK (C/CSPLIT)   // 64
#define BHALF (B/2)

typedef unsigned long long ull;

// Scratch (allocation-free: __device__ globals)
__device__ float  g_avg[B*C];
__device__ float  g_max[B*C];
__device__ float  g_wch[B*C];
__device__ float2 g_part[CSPLIT][B*HW]; // partial (max,sum) per channel-chunk
__device__ float2 g_cat2[B*HW];         // interleaved (maxmap, avgmap) per pixel
__device__ float  g_ws[B*HW];

// ---- packed f32x2 helpers (sm_100+) ----
__device__ __forceinline__ ull pack2(float a, float b) {
    ull r; asm("mov.b64 %0, {%1, %2};" : "=l"(r) : "f"(a), "f"(b)); return r;
}
__device__ __forceinline__ float2 unpack2(ull v) {
    float2 r; asm("mov.b64 {%0, %1}, %2;" : "=f"(r.x), "=f"(r.y) : "l"(v)); return r;
}
__device__ __forceinline__ ull ffma2(ull a, ull b, ull c) {
    ull d; asm("fma.rn.f32x2 %0, %1, %2, %3;" : "=l"(d) : "l"(a), "l"(b), "l"(c)); return d;
}
__device__ __forceinline__ ull fadd2(ull a, ull b) {
    ull d; asm("add.rn.f32x2 %0, %1, %2;" : "=l"(d) : "l"(a), "l"(b)); return d;
}
// streaming (evict-first) float4 load/store
__device__ __forceinline__ float4 ldcs4(const float4* p) {
    float4 v;
    asm("ld.global.cs.v4.f32 {%0,%1,%2,%3}, [%4];"
        : "=f"(v.x), "=f"(v.y), "=f"(v.z), "=f"(v.w) : "l"(p));
    return v;
}
__device__ __forceinline__ void stcs4(float4* p, float4 v) {
    asm volatile("st.global.cs.v4.f32 [%0], {%1,%2,%3,%4};"
                 :: "l"(p), "f"(v.x), "f"(v.y), "f"(v.z), "f"(v.w));
}

// ---------------- K1: per-(b,c) mean & max over H,W ----------------
__global__ __launch_bounds__(512) void k_reduce_hw(const float* __restrict__ x, int b0) {
    int bc = b0*C + blockIdx.x;
    const float4* xp = (const float4*)(x + (size_t)bc * HW);
    float s0 = 0.f, s1 = 0.f, s2 = 0.f, s3 = 0.f;
    float m0 = -INFINITY, m1 = -INFINITY, m2 = -INFINITY, m3 = -INFINITY;
    #pragma unroll
    for (int i = threadIdx.x; i < HW/16; i += 512) {
        float4 v0 = ldcs4(&xp[i]);
        float4 v1 = ldcs4(&xp[i +   HW/16]);
        float4 v2 = ldcs4(&xp[i + 2*HW/16]);
        float4 v3 = ldcs4(&xp[i + 3*HW/16]);
        s0 += (v0.x + v0.y) + (v0.z + v0.w);
        s1 += (v1.x + v1.y) + (v1.z + v1.w);
        s2 += (v2.x + v2.y) + (v2.z + v2.w);
        s3 += (v3.x + v3.y) + (v3.z + v3.w);
        m0 = fmaxf(m0, fmaxf(fmaxf(v0.x, v0.y), fmaxf(v0.z, v0.w)));
        m1 = fmaxf(m1, fmaxf(fmaxf(v1.x, v1.y), fmaxf(v1.z, v1.w)));
        m2 = fmaxf(m2, fmaxf(fmaxf(v2.x, v2.y), fmaxf(v2.z, v2.w)));
        m3 = fmaxf(m3, fmaxf(fmaxf(v3.x, v3.y), fmaxf(v3.z, v3.w)));
    }
    float s = (s0 + s1) + (s2 + s3);
    float m = fmaxf(fmaxf(m0, m1), fmaxf(m2, m3));
    #pragma unroll
    for (int o = 16; o; o >>= 1) {
        s += __shfl_xor_sync(0xffffffffu, s, o);
        m = fmaxf(m, __shfl_xor_sync(0xffffffffu, m, o));
    }
    __shared__ float ss[16], sm[16];
    int w = threadIdx.x >> 5, l = threadIdx.x & 31;
    if (l == 0) { ss[w] = s; sm[w] = m; }
    __syncthreads();
    if (threadIdx.x == 0) {
        for (int i = 1; i < 16; i++) { s += ss[i]; m = fmaxf(m, sm[i]); }
        g_avg[bc] = s * (1.f / HW);
        g_max[bc] = m;
    }
}

// ---------------- K2: channel MLP -> wch (tiny, grid=BHALF) ----------------
__global__ __launch_bounds__(256) void k_mlp(const float* __restrict__ w1, const float* __restrict__ b1,
                                             const float* __restrict__ w2, const float* __restrict__ b2,
                                             int b0) {
    int b = b0 + blockIdx.x;
    int t = threadIdx.x;
    __shared__ float s_avg[C], s_mx[C], s_h[R];
    s_avg[t] = g_avg[b*C + t];
    s_mx[t]  = g_max[b*C + t];
    __syncthreads();
    if (t < R) {
        float ha = b1[t], hm = b1[t];
        #pragma unroll 8
        for (int c = 0; c < C; c++) {
            float w = __ldg(&w1[t*C + c]);
            ha = fmaf(w, s_avg[c], ha);
            hm = fmaf(w, s_mx[c],  hm);
        }
        s_h[t] = fmaxf(ha, 0.f) + fmaxf(hm, 0.f);
    }
    __syncthreads();
    float o = 2.f * __ldg(&b2[t]);
    #pragma unroll
    for (int r = 0; r < R; r++) o = fmaf(__ldg(&w2[t*R + r]), s_h[r], o);
    g_wch[b*C + t] = 1.f / (1.f + __expf(-o));
}

// ---------------- K3: partial cat maps over 64 channels ----------------
// grid (HW/4/256, BHALF, CSPLIT), block 256
__global__ __launch_bounds__(256) void k_cat(const float* __restrict__ x, int b0) {
    int b  = b0 + blockIdx.y;
    int cz = blockIdx.z;
    int t  = threadIdx.x;
    __shared__ float sw[CCHUNK];
    if (t < CCHUNK) sw[t] = g_wch[b*C + cz*CCHUNK + t];
    __syncthreads();

    int p4 = blockIdx.x * 256 + t;   // float4 index within HW
    const float4* xb = (const float4*)(x + (size_t)b * C * HW + (size_t)cz*CCHUNK*HW);
    float4 s0 = make_float4(0.f,0.f,0.f,0.f), s1 = s0;
    float4 m0 = make_float4(-INFINITY,-INFINITY,-INFINITY,-INFINITY), m1 = m0;
    #pragma unroll 8
    for (int c = 0; c < CCHUNK; c += 2) {
        float4 v0 = ldcs4(&xb[(size_t)c     * (HW/4) + p4]);
        float4 v1 = ldcs4(&xb[(size_t)(c+1) * (HW/4) + p4]);
        float w0 = sw[c], w1v = sw[c+1];
        float a0 = w0*v0.x, a1 = w0*v0.y, a2 = w0*v0.z, a3 = w0*v0.w;
        float b0v = w1v*v1.x, b1v = w1v*v1.y, b2v = w1v*v1.z, b3 = w1v*v1.w;
        s0.x += a0; s0.y += a1; s0.z += a2; s0.w += a3;
        s1.x += b0v; s1.y += b1v; s1.z += b2v; s1.w += b3;
        m0.x = fmaxf(m0.x, a0); m0.y = fmaxf(m0.y, a1);
        m0.z = fmaxf(m0.z, a2); m0.w = fmaxf(m0.w, a3);
        m1.x = fmaxf(m1.x, b0v); m1.y = fmaxf(m1.y, b1v);
        m1.z = fmaxf(m1.z, b2v); m1.w = fmaxf(m1.w, b3);
    }
    float4 s = make_float4(s0.x+s1.x, s0.y+s1.y, s0.z+s1.z, s0.w+s1.w);
    float4 m = make_float4(fmaxf(m0.x,m1.x), fmaxf(m0.y,m1.y), fmaxf(m0.z,m1.z), fmaxf(m0.w,m1.w));

    float4* dst = (float4*)(g_part[cz] + (size_t)b*HW + (size_t)p4*4);
    dst[0] = make_float4(m.x, s.x, m.y, s.y);
    dst[1] = make_float4(m.z, s.z, m.w, s.w);
}

// ---------------- K3b: combine the CSPLIT partials -> g_cat2 ----------------
__global__ __launch_bounds__(256) void k_combine(int b0) {
    int i = b0*HW + blockIdx.x * blockDim.x + threadIdx.x;
    float2 a = g_part[0][i];
    float2 c = g_part[1][i];
    float2 d = g_part[2][i];
    float2 e = g_part[3][i];
    const float inv = 1.f / C;
    float2 o;
    o.x = fmaxf(fmaxf(a.x, c.x), fmaxf(d.x, e.x));
    o.y = ((a.y + c.y) + (d.y + e.y)) * inv;
    g_cat2[i] = o;
}

// ---------------- K4: offsets conv + deform conv + BN + sigmoid -> ws ----------------
// 2 pixels per thread (rows i0, i0+1); 4 independent FFMA2 chains per pixel-tap.
__global__ __launch_bounds__(128)
void k_deform(const float* __restrict__ off_w, const float* __restrict__ off_b,
              const float* __restrict__ dc_w,  const float* __restrict__ dc_b,
              const float* __restrict__ bn_gamma, const float* __restrict__ bn_beta,
              const float* __restrict__ bn_mean,  const float* __restrict__ bn_var,
              int b0) {
    __shared__ ull   s_wp[9][18];     // [tap][q] = (w_dy[q], w_dx[q])
    __shared__ ull   s_obp[9];        // (off_b[2k], off_b[2k+1])
    __shared__ float s_dw[18];
    __shared__ float2 trow[4][W];     // rows i0-1 .. i0+2 of (max,avg)

    int b  = b0 + (blockIdx.x >> 6);
    int i0 = (blockIdx.x & 63) * 2;
    int j  = threadIdx.x;

    for (int t = threadIdx.x; t < 162; t += 128) {
        int k = t / 18, q = t - k*18;
        s_wp[k][q] = pack2(off_w[(2*k)*18 + q], off_w[(2*k+1)*18 + q]);
    }
    if (threadIdx.x < 9)  s_obp[threadIdx.x] = pack2(off_b[2*threadIdx.x], off_b[2*threadIdx.x + 1]);
    if (threadIdx.x < 18) s_dw[threadIdx.x]  = dc_w[threadIdx.x];

    const float2* c2 = g_cat2 + (size_t)b*HW;

    #pragma unroll
    for (int r = 0; r < 4; r++) {
        int yy = i0 + r - 1;
        bool ok = (unsigned)yy < H;
        trow[r][j] = ok ? c2[yy*W + j] : make_float2(0.f, 0.f);
    }
    __syncthreads();

    ull na[4][3], nb[4][3];
    #pragma unroll
    for (int u = 0; u < 4; u++) {
        #pragma unroll
        for (int v = 0; v < 3; v++) {
            int xx = j + v - 1;
            bool ok = (unsigned)xx < W;
            int xc = min(max(xx, 0), W-1);
            float2 val = trow[u][xc];
            float vx = ok ? val.x : 0.f;
            float vy = ok ? val.y : 0.f;
            na[u][v] = pack2(vx, vx);
            nb[u][v] = pack2(vy, vy);
        }
    }

    const float dcb = __ldg(dc_b);
    float acc0 = dcb, acc1 = dcb;
    const float fj = (float)j;
    const float fi0 = (float)i0, fi1 = (float)(i0 + 1);

    #pragma unroll
    for (int k = 0; k < 9; k++) {
        const int ky = k / 3, kx = k % 3;
        ull p0a = s_obp[k], p0b = 0ull, p0c = 0ull, p0d = 0ull;
        ull p1a = s_obp[k], p1b = 0ull, p1c = 0ull, p1d = 0ull;
        #pragma unroll
        for (int q = 0; q < 9; q++) {
            int u = q / 3, v = q - u*3;
            ull w = s_wp[k][q];
            if (q < 5) { p0a = ffma2(w, na[u][v], p0a); p1a = ffma2(w, na[u+1][v], p1a); }
            else       { p0b = ffma2(w, na[u][v], p0b); p1b = ffma2(w, na[u+1][v], p1b); }
        }
        #pragma unroll
        for (int q = 0; q < 9; q++) {
            int u = q / 3, v = q - u*3;
            ull w = s_wp[k][9 + q];
            if (q < 5) { p0c = ffma2(w, nb[u][v], p0c); p1c = ffma2(w, nb[u+1][v], p1c); }
            else       { p0d = ffma2(w, nb[u][v], p0d); p1d = ffma2(w, nb[u+1][v], p1d); }
        }
        ull a0 = fadd2(fadd2(p0a, p0b), fadd2(p0c, p0d));
        ull a1 = fadd2(fadd2(p1a, p1b), fadd2(p1c, p1d));
        float2 o0 = unpack2(a0);
        float2 o1 = unpack2(a1);

        #pragma unroll
        for (int p = 0; p < 2; p++) {
            float py = (p ? fi1 : fi0) + (float)(ky - 1) + (p ? o1.x : o0.x);
            float px = fj + (float)(kx - 1) + (p ? o1.y : o0.y);
            float y0f = floorf(py), x0f = floorf(px);
            float wy = py - y0f, wx = px - x0f;
            float omwy = 1.f - wy, omwx = 1.f - wx;
            int y0 = (int)y0f, x0 = (int)x0f;

            ull s00 = 0ull, s01 = 0ull;
            #pragma unroll
            for (int dy = 0; dy < 2; dy++) {
                #pragma unroll
                for (int dx = 0; dx < 2; dx++) {
                    int yi = y0 + dy, xi = x0 + dx;
                    bool ok = ((unsigned)yi < H) & ((unsigned)xi < W);
                    float wgt = (dy ? wy : omwy) * (dx ? wx : omwx);
                    wgt = ok ? wgt : 0.f;
                    int idx = min(max(yi, 0), H-1) * W + min(max(xi, 0), W-1);
                    ull v = *(const ull*)(c2 + idx);
                    if (dy) s01 = ffma2(v, pack2(wgt, wgt), s01);
                    else    s00 = ffma2(v, pack2(wgt, wgt), s00);
                }
            }
            float2 sv = unpack2(fadd2(s00, s01));
            if (p) {
                acc1 = fmaf(sv.x, s_dw[k],     acc1);
                acc1 = fmaf(sv.y, s_dw[9 + k], acc1);
            } else {
                acc0 = fmaf(sv.x, s_dw[k],     acc0);
                acc0 = fmaf(sv.y, s_dw[9 + k], acc0);
            }
        }
    }

    float inv = __ldg(bn_gamma) * rsqrtf(__ldg(bn_var) + 1e-5f);
    float mean = __ldg(bn_mean), beta = __ldg(bn_beta);
    float d0 = (acc0 - mean) * inv + beta;
    float d1 = (acc1 - mean) * inv + beta;
    g_ws[b*HW + i0*W + j]       = 1.f / (1.f + __expf(-d0));
    g_ws[b*HW + (i0+1)*W + j]   = 1.f / (1.f + __expf(-d1));
}

// ---------------- K5: out = x * (1 + wch*ws) ----------------
__global__ __launch_bounds__(256) void k_final(const float* __restrict__ x, float* __restrict__ out,
                                               int b0) {
    size_t base = (size_t)b0*(C*HW/4) + (size_t)blockIdx.x * 512 + threadIdx.x;
    size_t e    = base << 2;
    int b  = (int)(e >> 22);            // C*HW = 2^22
    int c  = (int)(e >> 14) & (C - 1);  // uniform across the block
    float w = __ldg(&g_wch[b*C + c]);

    int hw0 = (int)e & (HW - 1);
    const float4* wsp = (const float4*)(g_ws + (size_t)b*HW);

    float4 xv0  = ldcs4((const float4*)x + base);
    float4 xv1  = ldcs4((const float4*)x + base + 256);
    float4 ws0  = __ldg(&wsp[hw0 >> 2]);
    float4 ws1  = __ldg(&wsp[(hw0 + 1024) >> 2]);

    float4 o0, o1;
    o0.x = xv0.x * fmaf(w, ws0.x, 1.f);
    o0.y = xv0.y * fmaf(w, ws0.y, 1.f);
    o0.z = xv0.z * fmaf(w, ws0.z, 1.f);
    o0.w = xv0.w * fmaf(w, ws0.w, 1.f);
    o1.x = xv1.x * fmaf(w, ws1.x, 1.f);
    o1.y = xv1.y * fmaf(w, ws1.y, 1.f);
    o1.z = xv1.z * fmaf(w, ws1.z, 1.f);
    o1.w = xv1.w * fmaf(w, ws1.w, 1.f);
    stcs4((float4*)out + base,       o0);
    stcs4((float4*)out + base + 256, o1);
}

static void launch_half(cudaStream_t st, int b0,
                        const float* x, float* out,
                        const float* w1, const float* b1,
                        const float* w2, const float* b2,
                        const float* off_w, const float* off_b,
                        const float* dc_w,  const float* dc_b,
                        const float* bng, const float* bnb,
                        const float* bnm, const float* bnv) {
    k_reduce_hw<<<BHALF*C, 512, 0, st>>>(x, b0);
    k_mlp<<<BHALF, C, 0, st>>>(w1, b1, w2, b2, b0);
    {
        dim3 grid(HW/4/256, BHALF, CSPLIT);
        k_cat<<<grid, 256, 0, st>>>(x, b0);
    }
    k_combine<<<(BHALF*HW)/256, 256, 0, st>>>(b0);
    k_deform<<<BHALF*H/2, 128, 0, st>>>(off_w, off_b, dc_w, dc_b, bng, bnb, bnm, bnv, b0);
    k_final<<<(BHALF*C*HW)/4/512, 256, 0, st>>>(x, out, b0);
}

extern "C" void kernel_launch(void* const* d_in, const int* in_sizes, int n_in,
                              void* d_out, int out_size) {
    const float* x     = (const float*)d_in[0];
    const float* w1    = (const float*)d_in[1];
    const float* b1    = (const float*)d_in[2];
    const float* w2    = (const float*)d_in[3];
    const float* b2    = (const float*)d_in[4];
    const float* off_w = (const float*)d_in[5];
    const float* off_b = (const float*)d_in[6];
    const float* dc_w  = (const float*)d_in[7];
    const float* dc_b  = (const float*)d_in[8];
    const float* bng   = (const float*)d_in[9];
    const float* bnb   = (const float*)d_in[10];
    const float* bnm   = (const float*)d_in[11];
    const float* bnv   = (const float*)d_in[12];
    float* out = (float*)d_out;

    // Fork a second stream off the capture (legacy) stream so the two
    // batch-half pipelines run concurrently; join before returning.
    cudaStream_t s1;
    cudaStreamCreateWithFlags(&s1, cudaStreamNonBlocking);
    cudaEvent_t e0, e1;
    cudaEventCreateWithFlags(&e0, cudaEventDisableTiming);
    cudaEventCreateWithFlags(&e1, cudaEventDisableTiming);

    cudaEventRecord(e0, 0);
    cudaStreamWaitEvent(s1, e0, 0);

    launch_half((cudaStream_t)0, 0,     x, out, w1, b1, w2, b2, off_w, off_b, dc_w, dc_b, bng, bnb, bnm, bnv);
    launch_half(s1,              BHALF, x, out, w1, b1, w2, b2, off_w, off_b, dc_w, dc_b, bng, bnb, bnm, bnv);

    cudaEventRecord(e1, s1);
    cudaStreamWaitEvent((cudaStream_t)0, e1, 0);
    // Note: s1/e0/e1 intentionally not destroyed mid-capture; kernel_launch
    // is invoked only a handful of times (correctness + capture), so the
    // handle leak is bounded and involves no device memory.
}

// round 15
// speedup vs baseline: 1.0604x; 1.0031x over previous
#include <cuda_runtime.h>
#include <math.h>

#define B 16
#define C 256
#define H 128
#define W 128
#define HW (H*W)
#define R 16
#define CSPLIT 4
#define CCHUNK (C/CSPLIT)   // 64
#define NQ 4
#define BQ (B/NQ)           // 4 batches per quarter

typedef unsigned long long ull;

// Scratch (allocation-free: __device__ globals)
__device__ float  g_avg[B*C];
__device__ float  g_max[B*C];
__device__ float  g_wch[B*C];
__device__ float2 g_part[CSPLIT][B*HW]; // partial (max,sum) per channel-chunk
__device__ float2 g_cat2[B*HW];         // interleaved (maxmap, avgmap) per pixel
__device__ float  g_ws[B*HW];

// ---- packed f32x2 helpers (sm_100+) ----
__device__ __forceinline__ ull pack2(float a, float b) {
    ull r; asm("mov.b64 %0, {%1, %2};" : "=l"(r) : "f"(a), "f"(b)); return r;
}
__device__ __forceinline__ float2 unpack2(ull v) {
    float2 r; asm("mov.b64 {%0, %1}, %2;" : "=f"(r.x), "=f"(r.y) : "l"(v)); return r;
}
__device__ __forceinline__ ull ffma2(ull a, ull b, ull c) {
    ull d; asm("fma.rn.f32x2 %0, %1, %2, %3;" : "=l"(d) : "l"(a), "l"(b), "l"(c)); return d;
}
__device__ __forceinline__ ull fadd2(ull a, ull b) {
    ull d; asm("add.rn.f32x2 %0, %1, %2;" : "=l"(d) : "l"(a), "l"(b)); return d;
}
// streaming (evict-first) float4 load/store
__device__ __forceinline__ float4 ldcs4(const float4* p) {
    float4 v;
    asm("ld.global.cs.v4.f32 {%0,%1,%2,%3}, [%4];"
        : "=f"(v.x), "=f"(v.y), "=f"(v.z), "=f"(v.w) : "l"(p));
    return v;
}
__device__ __forceinline__ void stcs4(float4* p, float4 v) {
    asm volatile("st.global.cs.v4.f32 [%0], {%1,%2,%3,%4};"
                 :: "l"(p), "f"(v.x), "f"(v.y), "f"(v.z), "f"(v.w));
}

// ---------------- K1: per-(b,c) mean & max over H,W ----------------
__global__ __launch_bounds__(512) void k_reduce_hw(const float* __restrict__ x, int b0) {
    int bc = b0*C + blockIdx.x;
    const float4* xp = (const float4*)(x + (size_t)bc * HW);
    float s0 = 0.f, s1 = 0.f, s2 = 0.f, s3 = 0.f;
    float m0 = -INFINITY, m1 = -INFINITY, m2 = -INFINITY, m3 = -INFINITY;
    #pragma unroll
    for (int i = threadIdx.x; i < HW/16; i += 512) {
        float4 v0 = ldcs4(&xp[i]);
        float4 v1 = ldcs4(&xp[i +   HW/16]);
        float4 v2 = ldcs4(&xp[i + 2*HW/16]);
        float4 v3 = ldcs4(&xp[i + 3*HW/16]);
        s0 += (v0.x + v0.y) + (v0.z + v0.w);
        s1 += (v1.x + v1.y) + (v1.z + v1.w);
        s2 += (v2.x + v2.y) + (v2.z + v2.w);
        s3 += (v3.x + v3.y) + (v3.z + v3.w);
        m0 = fmaxf(m0, fmaxf(fmaxf(v0.x, v0.y), fmaxf(v0.z, v0.w)));
        m1 = fmaxf(m1, fmaxf(fmaxf(v1.x, v1.y), fmaxf(v1.z, v1.w)));
        m2 = fmaxf(m2, fmaxf(fmaxf(v2.x, v2.y), fmaxf(v2.z, v2.w)));
        m3 = fmaxf(m3, fmaxf(fmaxf(v3.x, v3.y), fmaxf(v3.z, v3.w)));
    }
    float s = (s0 + s1) + (s2 + s3);
    float m = fmaxf(fmaxf(m0, m1), fmaxf(m2, m3));
    #pragma unroll
    for (int o = 16; o; o >>= 1) {
        s += __shfl_xor_sync(0xffffffffu, s, o);
        m = fmaxf(m, __shfl_xor_sync(0xffffffffu, m, o));
    }
    __shared__ float ss[16], sm[16];
    int w = threadIdx.x >> 5, l = threadIdx.x & 31;
    if (l == 0) { ss[w] = s; sm[w] = m; }
    __syncthreads();
    if (threadIdx.x == 0) {
        for (int i = 1; i < 16; i++) { s += ss[i]; m = fmaxf(m, sm[i]); }
        g_avg[bc] = s * (1.f / HW);
        g_max[bc] = m;
    }
}

// ---------------- K2: channel MLP -> wch (tiny, grid=BQ) ----------------
__global__ __launch_bounds__(256) void k_mlp(const float* __restrict__ w1, const float* __restrict__ b1,
                                             const float* __restrict__ w2, const float* __restrict__ b2,
                                             int b0) {
    int b = b0 + blockIdx.x;
    int t = threadIdx.x;
    __shared__ float s_avg[C], s_mx[C], s_h[R];
    s_avg[t] = g_avg[b*C + t];
    s_mx[t]  = g_max[b*C + t];
    __syncthreads();
    if (t < R) {
        float ha = b1[t], hm = b1[t];
        #pragma unroll 8
        for (int c = 0; c < C; c++) {
            float w = __ldg(&w1[t*C + c]);
            ha = fmaf(w, s_avg[c], ha);
            hm = fmaf(w, s_mx[c],  hm);
        }
        s_h[t] = fmaxf(ha, 0.f) + fmaxf(hm, 0.f);
    }
    __syncthreads();
    float o = 2.f * __ldg(&b2[t]);
    #pragma unroll
    for (int r = 0; r < R; r++) o = fmaf(__ldg(&w2[t*R + r]), s_h[r], o);
    g_wch[b*C + t] = 1.f / (1.f + __expf(-o));
}

// ---------------- K3: partial cat maps over 64 channels ----------------
// grid (HW/4/256, BQ, CSPLIT), block 256
__global__ __launch_bounds__(256) void k_cat(const float* __restrict__ x, int b0) {
    int b  = b0 + blockIdx.y;
    int cz = blockIdx.z;
    int t  = threadIdx.x;
    __shared__ float sw[CCHUNK];
    if (t < CCHUNK) sw[t] = g_wch[b*C + cz*CCHUNK + t];
    __syncthreads();

    int p4 = blockIdx.x * 256 + t;   // float4 index within HW
    const float4* xb = (const float4*)(x + (size_t)b * C * HW + (size_t)cz*CCHUNK*HW);
    float4 s0 = make_float4(0.f,0.f,0.f,0.f), s1 = s0;
    float4 m0 = make_float4(-INFINITY,-INFINITY,-INFINITY,-INFINITY), m1 = m0;
    #pragma unroll 8
    for (int c = 0; c < CCHUNK; c += 2) {
        float4 v0 = ldcs4(&xb[(size_t)c     * (HW/4) + p4]);
        float4 v1 = ldcs4(&xb[(size_t)(c+1) * (HW/4) + p4]);
        float w0 = sw[c], w1v = sw[c+1];
        float a0 = w0*v0.x, a1 = w0*v0.y, a2 = w0*v0.z, a3 = w0*v0.w;
        float b0v = w1v*v1.x, b1v = w1v*v1.y, b2v = w1v*v1.z, b3 = w1v*v1.w;
        s0.x += a0; s0.y += a1; s0.z += a2; s0.w += a3;
        s1.x += b0v; s1.y += b1v; s1.z += b2v; s1.w += b3;
        m0.x = fmaxf(m0.x, a0); m0.y = fmaxf(m0.y, a1);
        m0.z = fmaxf(m0.z, a2); m0.w = fmaxf(m0.w, a3);
        m1.x = fmaxf(m1.x, b0v); m1.y = fmaxf(m1.y, b1v);
        m1.z = fmaxf(m1.z, b2v); m1.w = fmaxf(m1.w, b3);
    }
    float4 s = make_float4(s0.x+s1.x, s0.y+s1.y, s0.z+s1.z, s0.w+s1.w);
    float4 m = make_float4(fmaxf(m0.x,m1.x), fmaxf(m0.y,m1.y), fmaxf(m0.z,m1.z), fmaxf(m0.w,m1.w));

    float4* dst = (float4*)(g_part[cz] + (size_t)b*HW + (size_t)p4*4);
    dst[0] = make_float4(m.x, s.x, m.y, s.y);
    dst[1] = make_float4(m.z, s.z, m.w, s.w);
}

// ---------------- K3b: combine the CSPLIT partials -> g_cat2 ----------------
__global__ __launch_bounds__(256) void k_combine(int b0) {
    int i = b0*HW + blockIdx.x * blockDim.x + threadIdx.x;
    float2 a = g_part[0][i];
    float2 c = g_part[1][i];
    float2 d = g_part[2][i];
    float2 e = g_part[3][i];
    const float inv = 1.f / C;
    float2 o;
    o.x = fmaxf(fmaxf(a.x, c.x), fmaxf(d.x, e.x));
    o.y = ((a.y + c.y) + (d.y + e.y)) * inv;
    g_cat2[i] = o;
}

// ---------------- K4: offsets conv + deform conv + BN + sigmoid -> ws ----------------
// 2 pixels per thread (rows i0, i0+1); 4 independent FFMA2 chains per pixel-tap.
__global__ __launch_bounds__(128)
void k_deform(const float* __restrict__ off_w, const float* __restrict__ off_b,
              const float* __restrict__ dc_w,  const float* __restrict__ dc_b,
              const float* __restrict__ bn_gamma, const float* __restrict__ bn_beta,
              const float* __restrict__ bn_mean,  const float* __restrict__ bn_var,
              int b0) {
    __shared__ ull   s_wp[9][18];     // [tap][q] = (w_dy[q], w_dx[q])
    __shared__ ull   s_obp[9];        // (off_b[2k], off_b[2k+1])
    __shared__ float s_dw[18];
    __shared__ float2 trow[4][W];     // rows i0-1 .. i0+2 of (max,avg)

    int b  = b0 + (blockIdx.x >> 6);
    int i0 = (blockIdx.x & 63) * 2;
    int j  = threadIdx.x;

    for (int t = threadIdx.x; t < 162; t += 128) {
        int k = t / 18, q = t - k*18;
        s_wp[k][q] = pack2(off_w[(2*k)*18 + q], off_w[(2*k+1)*18 + q]);
    }
    if (threadIdx.x < 9)  s_obp[threadIdx.x] = pack2(off_b[2*threadIdx.x], off_b[2*threadIdx.x + 1]);
    if (threadIdx.x < 18) s_dw[threadIdx.x]  = dc_w[threadIdx.x];

    const float2* c2 = g_cat2 + (size_t)b*HW;

    #pragma unroll
    for (int r = 0; r < 4; r++) {
        int yy = i0 + r - 1;
        bool ok = (unsigned)yy < H;
        trow[r][j] = ok ? c2[yy*W + j] : make_float2(0.f, 0.f);
    }
    __syncthreads();

    ull na[4][3], nb[4][3];
    #pragma unroll
    for (int u = 0; u < 4; u++) {
        #pragma unroll
        for (int v = 0; v < 3; v++) {
            int xx = j + v - 1;
            bool ok = (unsigned)xx < W;
            int xc = min(max(xx, 0), W-1);
            float2 val = trow[u][xc];
            float vx = ok ? val.x : 0.f;
            float vy = ok ? val.y : 0.f;
            na[u][v] = pack2(vx, vx);
            nb[u][v] = pack2(vy, vy);
        }
    }

    const float dcb = __ldg(dc_b);
    float acc0 = dcb, acc1 = dcb;
    const float fj = (float)j;
    const float fi0 = (float)i0, fi1 = (float)(i0 + 1);

    #pragma unroll
    for (int k = 0; k < 9; k++) {
        const int ky = k / 3, kx = k % 3;
        ull p0a = s_obp[k], p0b = 0ull, p0c = 0ull, p0d = 0ull;
        ull p1a = s_obp[k], p1b = 0ull, p1c = 0ull, p1d = 0ull;
        #pragma unroll
        for (int q = 0; q < 9; q++) {
            int u = q / 3, v = q - u*3;
            ull w = s_wp[k][q];
            if (q < 5) { p0a = ffma2(w, na[u][v], p0a); p1a = ffma2(w, na[u+1][v], p1a); }
            else       { p0b = ffma2(w, na[u][v], p0b); p1b = ffma2(w, na[u+1][v], p1b); }
        }
        #pragma unroll
        for (int q = 0; q < 9; q++) {
            int u = q / 3, v = q - u*3;
            ull w = s_wp[k][9 + q];
            if (q < 5) { p0c = ffma2(w, nb[u][v], p0c); p1c = ffma2(w, nb[u+1][v], p1c); }
            else       { p0d = ffma2(w, nb[u][v], p0d); p1d = ffma2(w, nb[u+1][v], p1d); }
        }
        ull a0 = fadd2(fadd2(p0a, p0b), fadd2(p0c, p0d));
        ull a1 = fadd2(fadd2(p1a, p1b), fadd2(p1c, p1d));
        float2 o0 = unpack2(a0);
        float2 o1 = unpack2(a1);

        #pragma unroll
        for (int p = 0; p < 2; p++) {
            float py = (p ? fi1 : fi0) + (float)(ky - 1) + (p ? o1.x : o0.x);
            float px = fj + (float)(kx - 1) + (p ? o1.y : o0.y);
            float y0f = floorf(py), x0f = floorf(px);
            float wy = py - y0f, wx = px - x0f;
            float omwy = 1.f - wy, omwx = 1.f - wx;
            int y0 = (int)y0f, x0 = (int)x0f;

            ull s00 = 0ull, s01 = 0ull;
            #pragma unroll
            for (int dy = 0; dy < 2; dy++) {
                #pragma unroll
                for (int dx = 0; dx < 2; dx++) {
                    int yi = y0 + dy, xi = x0 + dx;
                    bool ok = ((unsigned)yi < H) & ((unsigned)xi < W);
                    float wgt = (dy ? wy : omwy) * (dx ? wx : omwx);
                    wgt = ok ? wgt : 0.f;
                    int idx = min(max(yi, 0), H-1) * W + min(max(xi, 0), W-1);
                    ull v = *(const ull*)(c2 + idx);
                    if (dy) s01 = ffma2(v, pack2(wgt, wgt), s01);
                    else    s00 = ffma2(v, pack2(wgt, wgt), s00);
                }
            }
            float2 sv = unpack2(fadd2(s00, s01));
            if (p) {
                acc1 = fmaf(sv.x, s_dw[k],     acc1);
                acc1 = fmaf(sv.y, s_dw[9 + k], acc1);
            } else {
                acc0 = fmaf(sv.x, s_dw[k],     acc0);
                acc0 = fmaf(sv.y, s_dw[9 + k], acc0);
            }
        }
    }

    float inv = __ldg(bn_gamma) * rsqrtf(__ldg(bn_var) + 1e-5f);
    float mean = __ldg(bn_mean), beta = __ldg(bn_beta);
    float d0 = (acc0 - mean) * inv + beta;
    float d1 = (acc1 - mean) * inv + beta;
    g_ws[b*HW + i0*W + j]       = 1.f / (1.f + __expf(-d0));
    g_ws[b*HW + (i0+1)*W + j]   = 1.f / (1.f + __expf(-d1));
}

// ---------------- K5: out = x * (1 + wch*ws) ----------------
__global__ __launch_bounds__(256) void k_final(const float* __restrict__ x, float* __restrict__ out,
                                               int b0) {
    size_t base = (size_t)b0*(C*HW/4) + (size_t)blockIdx.x * 512 + threadIdx.x;
    size_t e    = base << 2;
    int b  = (int)(e >> 22);            // C*HW = 2^22
    int c  = (int)(e >> 14) & (C - 1);  // uniform across the block
    float w = __ldg(&g_wch[b*C + c]);

    int hw0 = (int)e & (HW - 1);
    const float4* wsp = (const float4*)(g_ws + (size_t)b*HW);

    float4 xv0  = ldcs4((const float4*)x + base);
    float4 xv1  = ldcs4((const float4*)x + base + 256);
    float4 ws0  = __ldg(&wsp[hw0 >> 2]);
    float4 ws1  = __ldg(&wsp[(hw0 + 1024) >> 2]);

    float4 o0, o1;
    o0.x = xv0.x * fmaf(w, ws0.x, 1.f);
    o0.y = xv0.y * fmaf(w, ws0.y, 1.f);
    o0.z = xv0.z * fmaf(w, ws0.z, 1.f);
    o0.w = xv0.w * fmaf(w, ws0.w, 1.f);
    o1.x = xv1.x * fmaf(w, ws1.x, 1.f);
    o1.y = xv1.y * fmaf(w, ws1.y, 1.f);
    o1.z = xv1.z * fmaf(w, ws1.z, 1.f);
    o1.w = xv1.w * fmaf(w, ws1.w, 1.f);
    stcs4((float4*)out + base,       o0);
    stcs4((float4*)out + base + 256, o1);
}

extern "C" void kernel_launch(void* const* d_in, const int* in_sizes, int n_in,
                              void* d_out, int out_size) {
    const float* x     = (const float*)d_in[0];
    const float* w1    = (const float*)d_in[1];
    const float* b1    = (const float*)d_in[2];
    const float* w2    = (const float*)d_in[3];
    const float* b2    = (const float*)d_in[4];
    const float* off_w = (const float*)d_in[5];
    const float* off_b = (const float*)d_in[6];
    const float* dc_w  = (const float*)d_in[7];
    const float* dc_b  = (const float*)d_in[8];
    const float* bng   = (const float*)d_in[9];
    const float* bnb   = (const float*)d_in[10];
    const float* bnm   = (const float*)d_in[11];
    const float* bnv   = (const float*)d_in[12];
    float* out = (float*)d_out;

    // 4 staggered quarter-pipelines: quarter q's K1 is chained on quarter
    // q-1's K1 completion, so low-util stages of early quarters overlap the
    // streaming stages of later ones. Quarter 0 runs on the capture (legacy)
    // stream; all others join back into it at the end.
    static cudaStream_t sq[NQ] = {0, 0, 0, 0};
    static cudaEvent_t  ek1[NQ], edone[NQ], efork;
    static bool init = false;
    if (!init) {
        for (int q = 1; q < NQ; q++) cudaStreamCreateWithFlags(&sq[q], cudaStreamNonBlocking);
        for (int q = 0; q < NQ; q++) {
            cudaEventCreateWithFlags(&ek1[q],   cudaEventDisableTiming);
            cudaEventCreateWithFlags(&edone[q], cudaEventDisableTiming);
        }
        cudaEventCreateWithFlags(&efork, cudaEventDisableTiming);
        init = true;
    }

    cudaEventRecord(efork, 0);
    for (int q = 1; q < NQ; q++) cudaStreamWaitEvent(sq[q], efork, 0);

    for (int q = 0; q < NQ; q++) {
        cudaStream_t st = sq[q];
        int b0 = q * BQ;
        if (q > 0) cudaStreamWaitEvent(st, ek1[q-1], 0);   // stagger
        k_reduce_hw<<<BQ*C, 512, 0, st>>>(x, b0);
        cudaEventRecord(ek1[q], st);
        k_mlp<<<BQ, C, 0, st>>>(w1, b1, w2, b2, b0);
        {
            dim3 grid(HW/4/256, BQ, CSPLIT);
            k_cat<<<grid, 256, 0, st>>>(x, b0);
        }
        k_combine<<<(BQ*HW)/256, 256, 0, st>>>(b0);
        k_deform<<<BQ*H/2, 128, 0, st>>>(off_w, off_b, dc_w, dc_b, bng, bnb, bnm, bnv, b0);
        k_final<<<(BQ*C*HW)/4/512, 256, 0, st>>>(x, out, b0);
        if (q > 0) cudaEventRecord(edone[q], st);
    }
    for (int q = 1; q < NQ; q++) cudaStreamWaitEvent((cudaStream_t)0, edone[q], 0);
}